// round 15
// baseline (speedup 1.0000x reference)
#include <cuda_runtime.h>
#include <cuda_bf16.h>
#include <cuda_fp16.h>
#include <cstdint>
#include <math.h>

#define DI __device__ __forceinline__

static constexpr int T_  = 8192;
static constexpr int H_  = 2048;
static constexpr int O_  = 2048;
static constexpr int E_  = 8;
static constexpr int R_  = 16;
static constexpr int ER_ = 128;
static constexpr float ALPHA_ = 16.0f;

// ---------------- scratch (__device__ globals) ------------------------------
__device__ __align__(256) __half g_xh [T_ * H_];    // fp16 x
__device__ __align__(256) __half g_wh [O_ * H_];    // fp16 W
__device__ __align__(256) __half g_ah [ER_ * H_];   // fp16 stacked A
__device__ __align__(256) __half g_bch[O_ * ER_];   // fp16 Bcat[o, e*16+r]
__device__ __align__(256) __half g_hw [T_ * ER_];   // fp16 scaled h
__device__ __align__(256) float  g_wmat[T_ * E_];

// ---------------- PTX helpers (base-ISA only) --------------------------------
DI uint32_t smem_u32(const void* p) {
    uint32_t a;
    asm("{ .reg .u64 t; cvta.to.shared.u64 t, %1; cvt.u32.u64 %0, t; }"
        : "=r"(a) : "l"(p));
    return a;
}
DI void cpasync16(uint32_t dst, const void* src) {
    asm volatile("cp.async.cg.shared.global [%0], [%1], 16;" :: "r"(dst), "l"(src));
}
DI void cp_commit() { asm volatile("cp.async.commit_group;" ::: "memory"); }
template <int N> DI void cp_wait() {
    asm volatile("cp.async.wait_group %0;" :: "n"(N) : "memory");
}
DI void ldm_x4(uint32_t* r, uint32_t a) {
    asm volatile("ldmatrix.sync.aligned.m8n8.x4.shared.b16 {%0,%1,%2,%3}, [%4];"
                 : "=r"(r[0]), "=r"(r[1]), "=r"(r[2]), "=r"(r[3]) : "r"(a));
}
DI void mma_f16(float* c, const uint32_t* a, uint32_t b0, uint32_t b1) {
    asm volatile(
        "mma.sync.aligned.m16n8k16.row.col.f32.f16.f16.f32 "
        "{%0,%1,%2,%3}, {%4,%5,%6,%7}, {%8,%9}, {%0,%1,%2,%3};"
        : "+f"(c[0]), "+f"(c[1]), "+f"(c[2]), "+f"(c[3])
        : "r"(a[0]), "r"(a[1]), "r"(a[2]), "r"(a[3]), "r"(b0), "r"(b1));
}

DI void st_half4(__half* dst, float4 v) {
    __half2 f0(__float2half_rn(v.x), __float2half_rn(v.y));
    __half2 f1(__float2half_rn(v.z), __float2half_rn(v.w));
    uint2 u = make_uint2(*reinterpret_cast<uint32_t*>(&f0),
                         *reinterpret_cast<uint32_t*>(&f1));
    *reinterpret_cast<uint2*>(dst) = u;
}

// ---------------- fused pre-kernel (unchanged from R14) -----------------------
static constexpr int NB_XB  = T_ / 2;                    // 4096 blocks, 2 tokens each
static constexpr int PN_W = O_ * H_ / 4;
static constexpr int PN_A = ER_ * H_ / 4;
static constexpr int PN_B = O_ * ER_ / 4;
static constexpr int PN_REST = PN_W + PN_A + PN_B;
static constexpr int NB_REST = (PN_REST + 255) / 256;    // 4608
static constexpr int NB_PRE  = NB_XB + NB_REST;

DI void rest_body(int i, const float* __restrict__ W,
                  const float* __restrict__ A, const float* __restrict__ Bsrc) {
    if (i < PN_W) {
        st_half4(g_wh + (size_t)4 * i, reinterpret_cast<const float4*>(W)[i]);
    } else if (i < PN_W + PN_A) {
        int j = i - PN_W;
        st_half4(g_ah + (size_t)4 * j, reinterpret_cast<const float4*>(A)[j]);
    } else if (i < PN_REST) {
        int j = i - (PN_W + PN_A);
        int o = j >> 5, c4 = (j & 31) * 4;
        int e = c4 >> 4, r = c4 & 15;
        const float* bp = Bsrc + ((size_t)e * O_ + o) * R_ + r;
        float4 v = make_float4(bp[0], bp[1], bp[2], bp[3]);
        st_half4(g_bch + (size_t)o * ER_ + c4, v);
    }
}

__global__ void __launch_bounds__(256) k_pre(const float* __restrict__ x,
                                             const float* __restrict__ W,
                                             const float* __restrict__ gw,
                                             const float* __restrict__ A,
                                             const float* __restrict__ Bsrc) {
    int bid = blockIdx.x, tid = threadIdx.x;
    if (bid < NB_XB) {
        __shared__ float red[2][4][8];
        int tok_local = tid >> 7;
        int li = tid & 127;
        int tG = bid * 2 + tok_local;
        const float4* xr  = reinterpret_cast<const float4*>(x + (size_t)tG * H_);
        const float4* gw4 = reinterpret_cast<const float4*>(gw);
        float acc[8];
#pragma unroll
        for (int e = 0; e < 8; e++) acc[e] = 0.f;
#pragma unroll
        for (int j = 0; j < 4; j++) {
            int f4 = li + j * 128;
            float4 v = xr[f4];
            st_half4(g_xh + (size_t)tG * H_ + f4 * 4, v);
#pragma unroll
            for (int e = 0; e < 8; e++) {
                float4 g4 = gw4[e * (H_ / 4) + f4];
                acc[e] += v.x * g4.x + v.y * g4.y + v.z * g4.z + v.w * g4.w;
            }
        }
#pragma unroll
        for (int off = 16; off > 0; off >>= 1)
#pragma unroll
            for (int e = 0; e < 8; e++)
                acc[e] += __shfl_down_sync(0xFFFFFFFFu, acc[e], off);
        int wit = (tid >> 5) & 3;
        if ((tid & 31) == 0)
#pragma unroll
            for (int e = 0; e < 8; e++) red[tok_local][wit][e] = acc[e];
        __syncthreads();
        if (tid < 2) {
            float l[8], m = -1e30f;
#pragma unroll
            for (int e = 0; e < 8; e++) {
                l[e] = red[tid][0][e] + red[tid][1][e] + red[tid][2][e] + red[tid][3][e];
                m = fmaxf(m, l[e]);
            }
            float p[8], sum = 0.f;
#pragma unroll
            for (int e = 0; e < 8; e++) { p[e] = expf(l[e] - m); sum += p[e]; }
#pragma unroll
            for (int e = 0; e < 8; e++) p[e] /= sum;
            int i1 = 0;
#pragma unroll
            for (int e = 1; e < 8; e++) if (p[e] > p[i1]) i1 = e;
            int i2 = (i1 == 0) ? 1 : 0;
#pragma unroll
            for (int e = 0; e < 8; e++) if (e != i1 && p[e] > p[i2]) i2 = e;
            float ws = p[i1] + p[i2];
            int tg = bid * 2 + tid;
#pragma unroll
            for (int e = 0; e < 8; e++) {
                float v = (e == i1) ? ALPHA_ * p[i1] / ws
                        : (e == i2) ? ALPHA_ * p[i2] / ws : 0.f;
                g_wmat[tg * 8 + e] = v;
            }
        }
    } else {
        int i = (bid - NB_XB) * 256 + tid;
        rest_body(i, W, A, Bsrc);
    }
}

// ---------------- GEMM engine: BK=64, 3 stages, frag double-buffer ------------
// pitch 144B (9 granules, gcd(9,8)=1): conflict-free cp.async stores + ldmatrix.
// MODE 0: main GEMM, CTA 128x256, 256 thr / 8 warps, 1 CTA/SM, NKT=34, grid 512
// MODE 1: h GEMM,    CTA  32x128, 128 thr / 4 warps, NKT=32, grid 256
static constexpr int PITCH_B = 144;
static constexpr int NSTAGE  = 3;

template <int MODE> struct Cfg {
    static constexpr int BM      = (MODE == 0) ? 128 : 32;
    static constexpr int BN      = (MODE == 0) ? 256 : 128;
    static constexpr int MT      = (MODE == 0) ? 4 : 1;
    static constexpr int WN      = (MODE == 0) ? 4 : 2;     // warps along N
    static constexpr int THREADS = (MODE == 0) ? 256 : 128;
    static constexpr int TILE_A  = BM * PITCH_B;
    static constexpr int TILE_BB = BN * PITCH_B;
    static constexpr int STAGE   = TILE_A + TILE_BB;
    static constexpr int SMEM    = NSTAGE * STAGE;
    static constexpr int NKT     = (MODE == 0) ? 34 : 32;
    static constexpr int MIN_CTA = (MODE == 0) ? 1 : 2;
};

template <int MODE>
DI void tile_src(int kt, int m0, int n0,
                 const __half*& As, const __half*& Bs, int& ld) {
    if (MODE == 1) {
        int k0 = kt * 64;
        As = g_xh + (size_t)m0 * H_ + k0;
        Bs = g_ah + k0;
        ld = H_;
    } else {
        if (kt < 32) {
            int k0 = kt * 64;
            As = g_xh + (size_t)m0 * H_ + k0;
            Bs = g_wh + (size_t)n0 * H_ + k0;
            ld = H_;
        } else {
            int k0 = (kt - 32) * 64;
            As = g_hw + (size_t)m0 * ER_ + k0;
            Bs = g_bch + (size_t)n0 * ER_ + k0;
            ld = ER_;
        }
    }
}

template <int MODE>
DI void load_tile(uint32_t sbase, int stage, int kt, int m0, int n0, int tid) {
    using C = Cfg<MODE>;
    const __half *As, *Bs;
    int ld;
    tile_src<MODE>(kt, m0, n0, As, Bs, ld);
    uint32_t sa = sbase + stage * C::STAGE;
    uint32_t sbB = sa + C::TILE_A;
#pragma unroll
    for (int j = 0; j < C::BM * 8 / C::THREADS; j++) {   // A: BM rows x 8 chunks
        int c = tid + j * C::THREADS;
        int row = c >> 3, kc = c & 7;
        uint32_t off = (uint32_t)row * PITCH_B + (uint32_t)kc * 16;
        cpasync16(sa + off, As + (size_t)row * ld + kc * 8);
    }
#pragma unroll
    for (int j = 0; j < C::BN * 8 / C::THREADS; j++) {   // B: BN rows x 8 chunks
        int c = tid + j * C::THREADS;
        int row = c >> 3, kc = c & 7;
        uint32_t off = (uint32_t)row * PITCH_B + (uint32_t)kc * 16;
        cpasync16(sbB + off, Bs + (size_t)row * ld + kc * 8);
    }
    cp_commit();
}

template <int MT>
DI void load_frags(int ks, uint32_t sa, uint32_t sbB, uint32_t aoff, uint32_t boff,
                   uint32_t af[][4], uint32_t bfr[][4]) {
#pragma unroll
    for (int mt = 0; mt < MT; mt++)
        ldm_x4(af[mt], sa + aoff + mt * (16 * PITCH_B) + ks * 32);
#pragma unroll
    for (int p = 0; p < 4; p++)
        ldm_x4(bfr[p], sbB + boff + p * (16 * PITCH_B) + ks * 32);
}

template <int MT>
DI void compute_stage(uint32_t sa, uint32_t sbB, float acc[][8][4],
                      uint32_t aoff, uint32_t boff) {
    uint32_t af[2][MT][4], bfr[2][4][4];
    load_frags<MT>(0, sa, sbB, aoff, boff, af[0], bfr[0]);
#pragma unroll
    for (int ks = 0; ks < 4; ks++) {
        int cur = ks & 1;
        if (ks < 3)
            load_frags<MT>(ks + 1, sa, sbB, aoff, boff, af[cur ^ 1], bfr[cur ^ 1]);
#pragma unroll
        for (int mt = 0; mt < MT; mt++)
#pragma unroll
            for (int nt = 0; nt < 8; nt++)
                mma_f16(acc[mt][nt], af[cur][mt],
                        bfr[cur][nt >> 1][(nt & 1) * 2],
                        bfr[cur][nt >> 1][(nt & 1) * 2 + 1]);
    }
}

template <int MODE>
__global__ void __launch_bounds__(Cfg<MODE>::THREADS, Cfg<MODE>::MIN_CTA)
k_gemm(float* __restrict__ out) {
    using C = Cfg<MODE>;
    extern __shared__ __align__(128) char smem[];
    uint32_t sbase = smem_u32(smem);
    int tid = threadIdx.x, lane = tid & 31, w = tid >> 5;
    int warp_m = w / C::WN, warp_n = w % C::WN;

    int m0, n0;
    if (MODE == 0) { m0 = (blockIdx.x & 63) * 128; n0 = (blockIdx.x >> 6) * 256; }
    else           { m0 = blockIdx.x * 32;         n0 = 0; }

    float acc[C::MT][8][4];
#pragma unroll
    for (int a = 0; a < C::MT; a++)
#pragma unroll
        for (int b = 0; b < 8; b++)
#pragma unroll
            for (int c = 0; c < 4; c++) acc[a][b][c] = 0.f;

    uint32_t aoff = (uint32_t)(warp_m * (C::MT * 16) + (lane & 7) + ((lane >> 3) & 1) * 8) * PITCH_B
                  + (uint32_t)(lane >> 4) * 16;
    uint32_t boff = (uint32_t)(warp_n * 64 + (lane & 7) + ((lane >> 4) & 1) * 8) * PITCH_B
                  + (uint32_t)((lane >> 3) & 1) * 16;

    load_tile<MODE>(sbase, 0, 0, m0, n0, tid);
    load_tile<MODE>(sbase, 1, 1, m0, n0, tid);

    int stage = 0;
    for (int kt = 0; kt < C::NKT; kt++) {
        cp_wait<1>();
        __syncthreads();
        if (kt + 2 < C::NKT) {
            int s2 = stage + 2; if (s2 >= NSTAGE) s2 -= NSTAGE;
            load_tile<MODE>(sbase, s2, kt + 2, m0, n0, tid);
        } else {
            cp_commit();
        }
        uint32_t sa = sbase + stage * C::STAGE;
        compute_stage<C::MT>(sa, sa + C::TILE_A, acc, aoff, boff);
        if (++stage == NSTAGE) stage = 0;
    }

    if (MODE == 0) {
#pragma unroll
        for (int mt = 0; mt < C::MT; mt++) {
            int r0 = m0 + warp_m * (C::MT * 16) + mt * 16 + (lane >> 2);
#pragma unroll
            for (int nt = 0; nt < 8; nt++) {
                int col = n0 + warp_n * 64 + nt * 8 + (lane & 3) * 2;
                float2 v01 = make_float2(acc[mt][nt][0], acc[mt][nt][1]);
                float2 v23 = make_float2(acc[mt][nt][2], acc[mt][nt][3]);
                *reinterpret_cast<float2*>(out + (size_t)r0 * O_ + col) = v01;
                *reinterpret_cast<float2*>(out + (size_t)(r0 + 8) * O_ + col) = v23;
            }
        }
    } else {
#pragma unroll
        for (int mt = 0; mt < C::MT; mt++) {
            int t0 = m0 + warp_m * (C::MT * 16) + mt * 16 + (lane >> 2);
#pragma unroll
            for (int nt = 0; nt < 8; nt++) {
                int j = warp_n * 64 + nt * 8 + (lane & 3) * 2;
#pragma unroll
                for (int half = 0; half < 2; half++) {
                    int t = t0 + half * 8;
                    float wm = g_wmat[t * 8 + (j >> 4)];
                    __half2 hv(__float2half_rn(acc[mt][nt][half * 2 + 0] * wm),
                               __float2half_rn(acc[mt][nt][half * 2 + 1] * wm));
                    *reinterpret_cast<uint32_t*>(g_hw + (size_t)t * ER_ + j) =
                        *reinterpret_cast<uint32_t*>(&hv);
                }
            }
        }
    }
}

// ---------------- launch ------------------------------------------------------
extern "C" void kernel_launch(void* const* d_in, const int* in_sizes, int n_in,
                              void* d_out, int out_size) {
    const float* x  = (const float*)d_in[0];
    const float* W  = (const float*)d_in[1];
    const float* gw = (const float*)d_in[2];
    const float* A  = (const float*)d_in[3];
    const float* B  = (const float*)d_in[4];
    float* out = (float*)d_out;

    cudaFuncSetAttribute(k_gemm<0>, cudaFuncAttributeMaxDynamicSharedMemorySize, Cfg<0>::SMEM);
    cudaFuncSetAttribute(k_gemm<1>, cudaFuncAttributeMaxDynamicSharedMemorySize, Cfg<1>::SMEM);

    k_pre<<<NB_PRE, 256>>>(x, W, gw, A, B);
    k_gemm<1><<<T_ / 32, Cfg<1>::THREADS, Cfg<1>::SMEM>>>(nullptr);
    k_gemm<0><<<(T_ / 128) * (O_ / 256), Cfg<0>::THREADS, Cfg<0>::SMEM>>>(out);
}

// round 16
// speedup vs baseline: 1.0997x; 1.0997x over previous
#include <cuda_runtime.h>
#include <cuda_bf16.h>
#include <cuda_fp16.h>
#include <cstdint>
#include <math.h>

#define DI __device__ __forceinline__

static constexpr int T_  = 8192;
static constexpr int H_  = 2048;
static constexpr int O_  = 2048;
static constexpr int E_  = 8;
static constexpr int R_  = 16;
static constexpr int ER_ = 128;
static constexpr float ALPHA_ = 16.0f;

// ---------------- scratch (__device__ globals) ------------------------------
__device__ __align__(256) __half g_xh [T_ * H_];    // fp16 x
__device__ __align__(256) __half g_wh [O_ * H_];    // fp16 W
__device__ __align__(256) __half g_ah [ER_ * H_];   // fp16 stacked A
__device__ __align__(256) __half g_bch[O_ * ER_];   // fp16 Bcat[o, e*16+r]
__device__ __align__(256) __half g_hw [T_ * ER_];   // fp16 scaled h
__device__ __align__(256) float  g_wmat[T_ * E_];
__device__ int g_hdone;                             // h-block completion counter

// ---------------- PTX helpers (base-ISA only) --------------------------------
DI uint32_t smem_u32(const void* p) {
    uint32_t a;
    asm("{ .reg .u64 t; cvta.to.shared.u64 t, %1; cvt.u32.u64 %0, t; }"
        : "=r"(a) : "l"(p));
    return a;
}
DI void cpasync16(uint32_t dst, const void* src) {
    asm volatile("cp.async.cg.shared.global [%0], [%1], 16;" :: "r"(dst), "l"(src));
}
DI void cp_commit() { asm volatile("cp.async.commit_group;" ::: "memory"); }
template <int N> DI void cp_wait() {
    asm volatile("cp.async.wait_group %0;" :: "n"(N) : "memory");
}
DI void ldm_x4(uint32_t* r, uint32_t a) {
    asm volatile("ldmatrix.sync.aligned.m8n8.x4.shared.b16 {%0,%1,%2,%3}, [%4];"
                 : "=r"(r[0]), "=r"(r[1]), "=r"(r[2]), "=r"(r[3]) : "r"(a));
}
DI void mma_f16(float* c, const uint32_t* a, uint32_t b0, uint32_t b1) {
    asm volatile(
        "mma.sync.aligned.m16n8k16.row.col.f32.f16.f16.f32 "
        "{%0,%1,%2,%3}, {%4,%5,%6,%7}, {%8,%9}, {%0,%1,%2,%3};"
        : "+f"(c[0]), "+f"(c[1]), "+f"(c[2]), "+f"(c[3])
        : "r"(a[0]), "r"(a[1]), "r"(a[2]), "r"(a[3]), "r"(b0), "r"(b1));
}

DI void st_half4(__half* dst, float4 v) {
    __half2 f0(__float2half_rn(v.x), __float2half_rn(v.y));
    __half2 f1(__float2half_rn(v.z), __float2half_rn(v.w));
    uint2 u = make_uint2(*reinterpret_cast<uint32_t*>(&f0),
                         *reinterpret_cast<uint32_t*>(&f1));
    *reinterpret_cast<uint2*>(dst) = u;
}

// ---------------- fused pre-kernel (R14; + g_hdone reset) ---------------------
static constexpr int NB_XB  = T_ / 2;                    // 4096 blocks, 2 tokens each
static constexpr int PN_W = O_ * H_ / 4;
static constexpr int PN_A = ER_ * H_ / 4;
static constexpr int PN_B = O_ * ER_ / 4;
static constexpr int PN_REST = PN_W + PN_A + PN_B;
static constexpr int NB_REST = (PN_REST + 255) / 256;    // 4608
static constexpr int NB_PRE  = NB_XB + NB_REST;

DI void rest_body(int i, const float* __restrict__ W,
                  const float* __restrict__ A, const float* __restrict__ Bsrc) {
    if (i < PN_W) {
        st_half4(g_wh + (size_t)4 * i, reinterpret_cast<const float4*>(W)[i]);
    } else if (i < PN_W + PN_A) {
        int j = i - PN_W;
        st_half4(g_ah + (size_t)4 * j, reinterpret_cast<const float4*>(A)[j]);
    } else if (i < PN_REST) {
        int j = i - (PN_W + PN_A);
        int o = j >> 5, c4 = (j & 31) * 4;
        int e = c4 >> 4, r = c4 & 15;
        const float* bp = Bsrc + ((size_t)e * O_ + o) * R_ + r;
        float4 v = make_float4(bp[0], bp[1], bp[2], bp[3]);
        st_half4(g_bch + (size_t)o * ER_ + c4, v);
    }
}

__global__ void __launch_bounds__(256) k_pre(const float* __restrict__ x,
                                             const float* __restrict__ W,
                                             const float* __restrict__ gw,
                                             const float* __restrict__ A,
                                             const float* __restrict__ Bsrc) {
    int bid = blockIdx.x, tid = threadIdx.x;
    if (bid == 0 && tid == 0) g_hdone = 0;   // reset inter-kernel flag each launch
    if (bid < NB_XB) {
        __shared__ float red[2][4][8];
        int tok_local = tid >> 7;
        int li = tid & 127;
        int tG = bid * 2 + tok_local;
        const float4* xr  = reinterpret_cast<const float4*>(x + (size_t)tG * H_);
        const float4* gw4 = reinterpret_cast<const float4*>(gw);
        float acc[8];
#pragma unroll
        for (int e = 0; e < 8; e++) acc[e] = 0.f;
#pragma unroll
        for (int j = 0; j < 4; j++) {
            int f4 = li + j * 128;
            float4 v = xr[f4];
            st_half4(g_xh + (size_t)tG * H_ + f4 * 4, v);
#pragma unroll
            for (int e = 0; e < 8; e++) {
                float4 g4 = gw4[e * (H_ / 4) + f4];
                acc[e] += v.x * g4.x + v.y * g4.y + v.z * g4.z + v.w * g4.w;
            }
        }
#pragma unroll
        for (int off = 16; off > 0; off >>= 1)
#pragma unroll
            for (int e = 0; e < 8; e++)
                acc[e] += __shfl_down_sync(0xFFFFFFFFu, acc[e], off);
        int wit = (tid >> 5) & 3;
        if ((tid & 31) == 0)
#pragma unroll
            for (int e = 0; e < 8; e++) red[tok_local][wit][e] = acc[e];
        __syncthreads();
        if (tid < 2) {
            float l[8], m = -1e30f;
#pragma unroll
            for (int e = 0; e < 8; e++) {
                l[e] = red[tid][0][e] + red[tid][1][e] + red[tid][2][e] + red[tid][3][e];
                m = fmaxf(m, l[e]);
            }
            float p[8], sum = 0.f;
#pragma unroll
            for (int e = 0; e < 8; e++) { p[e] = expf(l[e] - m); sum += p[e]; }
#pragma unroll
            for (int e = 0; e < 8; e++) p[e] /= sum;
            int i1 = 0;
#pragma unroll
            for (int e = 1; e < 8; e++) if (p[e] > p[i1]) i1 = e;
            int i2 = (i1 == 0) ? 1 : 0;
#pragma unroll
            for (int e = 0; e < 8; e++) if (e != i1 && p[e] > p[i2]) i2 = e;
            float ws = p[i1] + p[i2];
            int tg = bid * 2 + tid;
#pragma unroll
            for (int e = 0; e < 8; e++) {
                float v = (e == i1) ? ALPHA_ * p[i1] / ws
                        : (e == i2) ? ALPHA_ * p[i2] / ws : 0.f;
                g_wmat[tg * 8 + e] = v;
            }
        }
    } else {
        int i = (bid - NB_XB) * 256 + tid;
        rest_body(i, W, A, Bsrc);
    }
}

// ---------------- merged GEMM kernel ------------------------------------------
// Blocks [0,256): h GEMM (32x128, NKT=32) -> signal g_hdone.
// Blocks [256,1280): main GEMM (128x128, NKT=34); spin on g_hdone before
// prefetching lora tiles (kt+2==32). 128 threads, 2 CTAs/SM, BK=64, 3 stages.
static constexpr int PITCH_B = 144;
static constexpr int NSTAGE  = 3;
static constexpr int NB_H    = T_ / 32;                          // 256
static constexpr int NB_MAIN = (T_ / 128) * (O_ / 128);          // 1024

template <int MODE> struct Cfg {
    static constexpr int BM      = (MODE == 0) ? 128 : 32;
    static constexpr int MT      = (MODE == 0) ? 4 : 1;
    static constexpr int TILE_A  = BM * PITCH_B;
    static constexpr int TILE_BB = 128 * PITCH_B;
    static constexpr int STAGE   = TILE_A + TILE_BB;
    static constexpr int SMEM    = NSTAGE * STAGE;
    static constexpr int NKT     = (MODE == 0) ? 34 : 32;
};

template <int MODE>
DI void tile_src(int kt, int m0, int n0,
                 const __half*& As, const __half*& Bs, int& ld) {
    if (MODE == 1) {
        int k0 = kt * 64;
        As = g_xh + (size_t)m0 * H_ + k0;
        Bs = g_ah + k0;
        ld = H_;
    } else {
        if (kt < 32) {
            int k0 = kt * 64;
            As = g_xh + (size_t)m0 * H_ + k0;
            Bs = g_wh + (size_t)n0 * H_ + k0;
            ld = H_;
        } else {
            int k0 = (kt - 32) * 64;
            As = g_hw + (size_t)m0 * ER_ + k0;
            Bs = g_bch + (size_t)n0 * ER_ + k0;
            ld = ER_;
        }
    }
}

template <int MODE>
DI void load_tile(uint32_t sbase, int stage, int kt, int m0, int n0, int tid) {
    using C = Cfg<MODE>;
    const __half *As, *Bs;
    int ld;
    tile_src<MODE>(kt, m0, n0, As, Bs, ld);
    uint32_t sa = sbase + stage * C::STAGE;
    uint32_t sbB = sa + C::TILE_A;
#pragma unroll
    for (int j = 0; j < C::BM / 16; j++) {       // A: BM rows x 8 chunks
        int c = tid + j * 128;
        int row = c >> 3, kc = c & 7;
        uint32_t off = (uint32_t)row * PITCH_B + (uint32_t)kc * 16;
        cpasync16(sa + off, As + (size_t)row * ld + kc * 8);
    }
#pragma unroll
    for (int j = 0; j < 8; j++) {                // B: 128 rows x 8 chunks
        int c = tid + j * 128;
        int row = c >> 3, kc = c & 7;
        uint32_t off = (uint32_t)row * PITCH_B + (uint32_t)kc * 16;
        cpasync16(sbB + off, Bs + (size_t)row * ld + kc * 8);
    }
    cp_commit();
}

template <int MT>
DI void load_frags(int ks, uint32_t sa, uint32_t sbB, uint32_t aoff, uint32_t boff,
                   uint32_t af[][4], uint32_t bfr[][4]) {
#pragma unroll
    for (int mt = 0; mt < MT; mt++)
        ldm_x4(af[mt], sa + aoff + mt * (16 * PITCH_B) + ks * 32);
#pragma unroll
    for (int p = 0; p < 4; p++)
        ldm_x4(bfr[p], sbB + boff + p * (16 * PITCH_B) + ks * 32);
}

template <int MT>
DI void compute_stage(uint32_t sa, uint32_t sbB, float acc[][8][4],
                      uint32_t aoff, uint32_t boff) {
    uint32_t af[2][MT][4], bfr[2][4][4];
    load_frags<MT>(0, sa, sbB, aoff, boff, af[0], bfr[0]);
#pragma unroll
    for (int ks = 0; ks < 4; ks++) {
        int cur = ks & 1;
        if (ks < 3)
            load_frags<MT>(ks + 1, sa, sbB, aoff, boff, af[cur ^ 1], bfr[cur ^ 1]);
#pragma unroll
        for (int mt = 0; mt < MT; mt++)
#pragma unroll
            for (int nt = 0; nt < 8; nt++)
                mma_f16(acc[mt][nt], af[cur][mt],
                        bfr[cur][nt >> 1][(nt & 1) * 2],
                        bfr[cur][nt >> 1][(nt & 1) * 2 + 1]);
    }
}

template <int MODE>
DI void gemm_body(uint32_t sbase, int m0, int n0, int tid, float* __restrict__ out) {
    using C = Cfg<MODE>;
    int lane = tid & 31, w = tid >> 5;
    int warp_m = w >> 1, warp_n = w & 1;

    float acc[C::MT][8][4];
#pragma unroll
    for (int a = 0; a < C::MT; a++)
#pragma unroll
        for (int b = 0; b < 8; b++)
#pragma unroll
            for (int c = 0; c < 4; c++) acc[a][b][c] = 0.f;

    uint32_t aoff = (uint32_t)(warp_m * (C::MT * 16) + (lane & 7) + ((lane >> 3) & 1) * 8) * PITCH_B
                  + (uint32_t)(lane >> 4) * 16;
    uint32_t boff = (uint32_t)(warp_n * 64 + (lane & 7) + ((lane >> 4) & 1) * 8) * PITCH_B
                  + (uint32_t)((lane >> 3) & 1) * 16;

    load_tile<MODE>(sbase, 0, 0, m0, n0, tid);
    load_tile<MODE>(sbase, 1, 1, m0, n0, tid);

    int stage = 0;
    for (int kt = 0; kt < C::NKT; kt++) {
        cp_wait<1>();
        __syncthreads();
        if (MODE == 0 && kt == 30) {             // next prefetch reads g_hw
            if (tid == 0) {
                while (*(volatile int*)&g_hdone < NB_H) {}
                __threadfence();
            }
            __syncthreads();
        }
        if (kt + 2 < C::NKT) {
            int s2 = stage + 2; if (s2 >= NSTAGE) s2 -= NSTAGE;
            load_tile<MODE>(sbase, s2, kt + 2, m0, n0, tid);
        } else {
            cp_commit();
        }
        uint32_t sa = sbase + stage * C::STAGE;
        compute_stage<C::MT>(sa, sa + C::TILE_A, acc, aoff, boff);
        if (++stage == NSTAGE) stage = 0;
    }

    if (MODE == 0) {
#pragma unroll
        for (int mt = 0; mt < C::MT; mt++) {
            int r0 = m0 + warp_m * (C::MT * 16) + mt * 16 + (lane >> 2);
#pragma unroll
            for (int nt = 0; nt < 8; nt++) {
                int col = n0 + warp_n * 64 + nt * 8 + (lane & 3) * 2;
                float2 v01 = make_float2(acc[mt][nt][0], acc[mt][nt][1]);
                float2 v23 = make_float2(acc[mt][nt][2], acc[mt][nt][3]);
                *reinterpret_cast<float2*>(out + (size_t)r0 * O_ + col) = v01;
                *reinterpret_cast<float2*>(out + (size_t)(r0 + 8) * O_ + col) = v23;
            }
        }
    } else {
#pragma unroll
        for (int mt = 0; mt < C::MT; mt++) {
            int t0 = m0 + warp_m * (C::MT * 16) + mt * 16 + (lane >> 2);
#pragma unroll
            for (int nt = 0; nt < 8; nt++) {
                int j = warp_n * 64 + nt * 8 + (lane & 3) * 2;
#pragma unroll
                for (int half = 0; half < 2; half++) {
                    int t = t0 + half * 8;
                    float wm = g_wmat[t * 8 + (j >> 4)];
                    __half2 hv(__float2half_rn(acc[mt][nt][half * 2 + 0] * wm),
                               __float2half_rn(acc[mt][nt][half * 2 + 1] * wm));
                    *reinterpret_cast<uint32_t*>(g_hw + (size_t)t * ER_ + j) =
                        *reinterpret_cast<uint32_t*>(&hv);
                }
            }
        }
        __syncthreads();
        if (tid == 0) {
            __threadfence();
            atomicAdd(&g_hdone, 1);
        }
    }
}

__global__ void __launch_bounds__(128, 2) k_gemm_all(float* __restrict__ out) {
    extern __shared__ __align__(128) char smem[];
    uint32_t sbase = smem_u32(smem);
    int bid = blockIdx.x, tid = threadIdx.x;
    if (bid < NB_H) {
        gemm_body<1>(sbase, bid * 32, 0, tid, nullptr);
    } else {
        int b = bid - NB_H;
        gemm_body<0>(sbase, (b & 63) * 128, (b >> 6) * 128, tid, out);
    }
}

// ---------------- launch ------------------------------------------------------
extern "C" void kernel_launch(void* const* d_in, const int* in_sizes, int n_in,
                              void* d_out, int out_size) {
    const float* x  = (const float*)d_in[0];
    const float* W  = (const float*)d_in[1];
    const float* gw = (const float*)d_in[2];
    const float* A  = (const float*)d_in[3];
    const float* B  = (const float*)d_in[4];
    float* out = (float*)d_out;

    cudaFuncSetAttribute(k_gemm_all, cudaFuncAttributeMaxDynamicSharedMemorySize,
                         Cfg<0>::SMEM);

    k_pre<<<NB_PRE, 256>>>(x, W, gw, A, B);
    k_gemm_all<<<NB_H + NB_MAIN, 128, Cfg<0>::SMEM>>>(out);
}

// round 17
// speedup vs baseline: 1.1583x; 1.0534x over previous
#include <cuda_runtime.h>
#include <cuda_bf16.h>
#include <cuda_fp16.h>
#include <cstdint>
#include <math.h>

#define DI __device__ __forceinline__

static constexpr int T_  = 8192;
static constexpr int H_  = 2048;
static constexpr int O_  = 2048;
static constexpr int E_  = 8;
static constexpr int R_  = 16;
static constexpr int ER_ = 128;
static constexpr float ALPHA_ = 16.0f;

// ---------------- scratch (__device__ globals) ------------------------------
__device__ __align__(256) __half g_xh [T_ * H_];    // fp16 x
__device__ __align__(256) __half g_wh [O_ * H_];    // fp16 W
__device__ __align__(256) __half g_ah [ER_ * H_];   // fp16 stacked A
__device__ __align__(256) __half g_bch[O_ * ER_];   // fp16 Bcat[o, e*16+r]
__device__ __align__(256) __half g_hw [T_ * ER_];   // fp16 scaled h
__device__ __align__(256) float  g_wmat[T_ * E_];
__device__ int g_hdone;                             // h-block completion counter

// ---------------- PTX helpers (base-ISA only) --------------------------------
DI uint32_t smem_u32(const void* p) {
    uint32_t a;
    asm("{ .reg .u64 t; cvta.to.shared.u64 t, %1; cvt.u32.u64 %0, t; }"
        : "=r"(a) : "l"(p));
    return a;
}
DI void cpasync16(uint32_t dst, const void* src) {
    asm volatile("cp.async.cg.shared.global [%0], [%1], 16;" :: "r"(dst), "l"(src));
}
DI void cp_commit() { asm volatile("cp.async.commit_group;" ::: "memory"); }
template <int N> DI void cp_wait() {
    asm volatile("cp.async.wait_group %0;" :: "n"(N) : "memory");
}
DI void ldm_x4(uint32_t* r, uint32_t a) {
    asm volatile("ldmatrix.sync.aligned.m8n8.x4.shared.b16 {%0,%1,%2,%3}, [%4];"
                 : "=r"(r[0]), "=r"(r[1]), "=r"(r[2]), "=r"(r[3]) : "r"(a));
}
DI void mma_f16(float* c, const uint32_t* a, uint32_t b0, uint32_t b1) {
    asm volatile(
        "mma.sync.aligned.m16n8k16.row.col.f32.f16.f16.f32 "
        "{%0,%1,%2,%3}, {%4,%5,%6,%7}, {%8,%9}, {%0,%1,%2,%3};"
        : "+f"(c[0]), "+f"(c[1]), "+f"(c[2]), "+f"(c[3])
        : "r"(a[0]), "r"(a[1]), "r"(a[2]), "r"(a[3]), "r"(b0), "r"(b1));
}

DI void st_half4(__half* dst, float4 v) {
    __half2 f0(__float2half_rn(v.x), __float2half_rn(v.y));
    __half2 f1(__float2half_rn(v.z), __float2half_rn(v.w));
    uint2 u = make_uint2(*reinterpret_cast<uint32_t*>(&f0),
                         *reinterpret_cast<uint32_t*>(&f1));
    *reinterpret_cast<uint2*>(dst) = u;
}

// ---------------- fused pre-kernel -------------------------------------------
// x-blocks: 4 tokens/block, each thread handles 2 tokens so every gw float4
// is loaded once and reused (halves gw L1 traffic). Router math is bitwise
// identical to R14/R16. Remaining blocks stream W/A/Bcat -> fp16.
static constexpr int NB_XB  = T_ / 4;                    // 2048 blocks, 4 tokens each
static constexpr int PN_W = O_ * H_ / 4;
static constexpr int PN_A = ER_ * H_ / 4;
static constexpr int PN_B = O_ * ER_ / 4;
static constexpr int PN_REST = PN_W + PN_A + PN_B;
static constexpr int NB_REST = (PN_REST + 255) / 256;    // 4608
static constexpr int NB_PRE  = NB_XB + NB_REST;

DI void rest_body(int i, const float* __restrict__ W,
                  const float* __restrict__ A, const float* __restrict__ Bsrc) {
    if (i < PN_W) {
        st_half4(g_wh + (size_t)4 * i, reinterpret_cast<const float4*>(W)[i]);
    } else if (i < PN_W + PN_A) {
        int j = i - PN_W;
        st_half4(g_ah + (size_t)4 * j, reinterpret_cast<const float4*>(A)[j]);
    } else if (i < PN_REST) {
        int j = i - (PN_W + PN_A);
        int o = j >> 5, c4 = (j & 31) * 4;
        int e = c4 >> 4, r = c4 & 15;
        const float* bp = Bsrc + ((size_t)e * O_ + o) * R_ + r;
        float4 v = make_float4(bp[0], bp[1], bp[2], bp[3]);
        st_half4(g_bch + (size_t)o * ER_ + c4, v);
    }
}

__global__ void __launch_bounds__(256) k_pre(const float* __restrict__ x,
                                             const float* __restrict__ W,
                                             const float* __restrict__ gw,
                                             const float* __restrict__ A,
                                             const float* __restrict__ Bsrc) {
    int bid = blockIdx.x, tid = threadIdx.x;
    if (bid == 0 && tid == 0) g_hdone = 0;   // reset inter-kernel flag each launch
    if (bid < NB_XB) {
        __shared__ float red[4][4][8];
        int half = tid >> 7;                 // 0: tokens 0,1; 1: tokens 2,3
        int li = tid & 127;
        int t0 = bid * 4 + half * 2;
        const float4* xr0 = reinterpret_cast<const float4*>(x + (size_t)t0 * H_);
        const float4* xr1 = reinterpret_cast<const float4*>(x + (size_t)(t0 + 1) * H_);
        const float4* gw4 = reinterpret_cast<const float4*>(gw);
        float a0[8], a1[8];
#pragma unroll
        for (int e = 0; e < 8; e++) { a0[e] = 0.f; a1[e] = 0.f; }
#pragma unroll
        for (int j = 0; j < 4; j++) {
            int f4 = li + j * 128;
            float4 v0 = xr0[f4];
            float4 v1 = xr1[f4];
            st_half4(g_xh + (size_t)t0 * H_ + f4 * 4, v0);
            st_half4(g_xh + (size_t)(t0 + 1) * H_ + f4 * 4, v1);
#pragma unroll
            for (int e = 0; e < 8; e++) {
                float4 g4 = gw4[e * (H_ / 4) + f4];   // loaded once, used twice
                a0[e] += v0.x * g4.x + v0.y * g4.y + v0.z * g4.z + v0.w * g4.w;
                a1[e] += v1.x * g4.x + v1.y * g4.y + v1.z * g4.z + v1.w * g4.w;
            }
        }
#pragma unroll
        for (int off = 16; off > 0; off >>= 1)
#pragma unroll
            for (int e = 0; e < 8; e++) {
                a0[e] += __shfl_down_sync(0xFFFFFFFFu, a0[e], off);
                a1[e] += __shfl_down_sync(0xFFFFFFFFu, a1[e], off);
            }
        int wit = (tid >> 5) & 3;            // warp index within half
        if ((tid & 31) == 0)
#pragma unroll
            for (int e = 0; e < 8; e++) {
                red[half * 2 + 0][wit][e] = a0[e];
                red[half * 2 + 1][wit][e] = a1[e];
            }
        __syncthreads();
        if (tid < 4) {
            float l[8], m = -1e30f;
#pragma unroll
            for (int e = 0; e < 8; e++) {
                l[e] = red[tid][0][e] + red[tid][1][e] + red[tid][2][e] + red[tid][3][e];
                m = fmaxf(m, l[e]);
            }
            float p[8], sum = 0.f;
#pragma unroll
            for (int e = 0; e < 8; e++) { p[e] = expf(l[e] - m); sum += p[e]; }
#pragma unroll
            for (int e = 0; e < 8; e++) p[e] /= sum;
            int i1 = 0;
#pragma unroll
            for (int e = 1; e < 8; e++) if (p[e] > p[i1]) i1 = e;
            int i2 = (i1 == 0) ? 1 : 0;
#pragma unroll
            for (int e = 0; e < 8; e++) if (e != i1 && p[e] > p[i2]) i2 = e;
            float ws = p[i1] + p[i2];
            int tg = bid * 4 + tid;
#pragma unroll
            for (int e = 0; e < 8; e++) {
                float v = (e == i1) ? ALPHA_ * p[i1] / ws
                        : (e == i2) ? ALPHA_ * p[i2] / ws : 0.f;
                g_wmat[tg * 8 + e] = v;
            }
        }
    } else {
        int i = (bid - NB_XB) * 256 + tid;
        rest_body(i, W, A, Bsrc);
    }
}

// ---------------- merged GEMM kernel ------------------------------------------
// Blocks [0,128): h GEMM (64x128, MT=2, NKT=32) -> signal g_hdone.
// Blocks [128,1152): main GEMM (128x128, NKT=34); spin on g_hdone before
// prefetching lora tiles (kt+2==32). 128 threads, 2 CTAs/SM, BK=64, 3 stages.
static constexpr int PITCH_B = 144;
static constexpr int NSTAGE  = 3;
static constexpr int NB_H    = T_ / 64;                          // 128
static constexpr int NB_MAIN = (T_ / 128) * (O_ / 128);          // 1024

template <int MODE> struct Cfg {
    static constexpr int BM      = (MODE == 0) ? 128 : 64;
    static constexpr int MT      = (MODE == 0) ? 4 : 2;
    static constexpr int TILE_A  = BM * PITCH_B;
    static constexpr int TILE_BB = 128 * PITCH_B;
    static constexpr int STAGE   = TILE_A + TILE_BB;
    static constexpr int SMEM    = NSTAGE * STAGE;
    static constexpr int NKT     = (MODE == 0) ? 34 : 32;
};

template <int MODE>
DI void tile_src(int kt, int m0, int n0,
                 const __half*& As, const __half*& Bs, int& ld) {
    if (MODE == 1) {
        int k0 = kt * 64;
        As = g_xh + (size_t)m0 * H_ + k0;
        Bs = g_ah + k0;
        ld = H_;
    } else {
        if (kt < 32) {
            int k0 = kt * 64;
            As = g_xh + (size_t)m0 * H_ + k0;
            Bs = g_wh + (size_t)n0 * H_ + k0;
            ld = H_;
        } else {
            int k0 = (kt - 32) * 64;
            As = g_hw + (size_t)m0 * ER_ + k0;
            Bs = g_bch + (size_t)n0 * ER_ + k0;
            ld = ER_;
        }
    }
}

template <int MODE>
DI void load_tile(uint32_t sbase, int stage, int kt, int m0, int n0, int tid) {
    using C = Cfg<MODE>;
    const __half *As, *Bs;
    int ld;
    tile_src<MODE>(kt, m0, n0, As, Bs, ld);
    uint32_t sa = sbase + stage * C::STAGE;
    uint32_t sbB = sa + C::TILE_A;
#pragma unroll
    for (int j = 0; j < C::BM / 16; j++) {       // A: BM rows x 8 chunks
        int c = tid + j * 128;
        int row = c >> 3, kc = c & 7;
        uint32_t off = (uint32_t)row * PITCH_B + (uint32_t)kc * 16;
        cpasync16(sa + off, As + (size_t)row * ld + kc * 8);
    }
#pragma unroll
    for (int j = 0; j < 8; j++) {                // B: 128 rows x 8 chunks
        int c = tid + j * 128;
        int row = c >> 3, kc = c & 7;
        uint32_t off = (uint32_t)row * PITCH_B + (uint32_t)kc * 16;
        cpasync16(sbB + off, Bs + (size_t)row * ld + kc * 8);
    }
    cp_commit();
}

template <int MT>
DI void load_frags(int ks, uint32_t sa, uint32_t sbB, uint32_t aoff, uint32_t boff,
                   uint32_t af[][4], uint32_t bfr[][4]) {
#pragma unroll
    for (int mt = 0; mt < MT; mt++)
        ldm_x4(af[mt], sa + aoff + mt * (16 * PITCH_B) + ks * 32);
#pragma unroll
    for (int p = 0; p < 4; p++)
        ldm_x4(bfr[p], sbB + boff + p * (16 * PITCH_B) + ks * 32);
}

template <int MT>
DI void compute_stage(uint32_t sa, uint32_t sbB, float acc[][8][4],
                      uint32_t aoff, uint32_t boff) {
    uint32_t af[2][MT][4], bfr[2][4][4];
    load_frags<MT>(0, sa, sbB, aoff, boff, af[0], bfr[0]);
#pragma unroll
    for (int ks = 0; ks < 4; ks++) {
        int cur = ks & 1;
        if (ks < 3)
            load_frags<MT>(ks + 1, sa, sbB, aoff, boff, af[cur ^ 1], bfr[cur ^ 1]);
#pragma unroll
        for (int mt = 0; mt < MT; mt++)
#pragma unroll
            for (int nt = 0; nt < 8; nt++)
                mma_f16(acc[mt][nt], af[cur][mt],
                        bfr[cur][nt >> 1][(nt & 1) * 2],
                        bfr[cur][nt >> 1][(nt & 1) * 2 + 1]);
    }
}

template <int MODE>
DI void gemm_body(uint32_t sbase, int m0, int n0, int tid, float* __restrict__ out) {
    using C = Cfg<MODE>;
    int lane = tid & 31, w = tid >> 5;
    int warp_m = w >> 1, warp_n = w & 1;

    float acc[C::MT][8][4];
#pragma unroll
    for (int a = 0; a < C::MT; a++)
#pragma unroll
        for (int b = 0; b < 8; b++)
#pragma unroll
            for (int c = 0; c < 4; c++) acc[a][b][c] = 0.f;

    uint32_t aoff = (uint32_t)(warp_m * (C::MT * 16) + (lane & 7) + ((lane >> 3) & 1) * 8) * PITCH_B
                  + (uint32_t)(lane >> 4) * 16;
    uint32_t boff = (uint32_t)(warp_n * 64 + (lane & 7) + ((lane >> 4) & 1) * 8) * PITCH_B
                  + (uint32_t)((lane >> 3) & 1) * 16;

    load_tile<MODE>(sbase, 0, 0, m0, n0, tid);
    load_tile<MODE>(sbase, 1, 1, m0, n0, tid);

    int stage = 0;
    for (int kt = 0; kt < C::NKT; kt++) {
        cp_wait<1>();
        __syncthreads();
        if (MODE == 0 && kt == 30) {             // next prefetch reads g_hw
            if (tid == 0) {
                while (*(volatile int*)&g_hdone < NB_H) {}
                __threadfence();
            }
            __syncthreads();
        }
        if (kt + 2 < C::NKT) {
            int s2 = stage + 2; if (s2 >= NSTAGE) s2 -= NSTAGE;
            load_tile<MODE>(sbase, s2, kt + 2, m0, n0, tid);
        } else {
            cp_commit();
        }
        uint32_t sa = sbase + stage * C::STAGE;
        compute_stage<C::MT>(sa, sa + C::TILE_A, acc, aoff, boff);
        if (++stage == NSTAGE) stage = 0;
    }

    if (MODE == 0) {
#pragma unroll
        for (int mt = 0; mt < C::MT; mt++) {
            int r0 = m0 + warp_m * (C::MT * 16) + mt * 16 + (lane >> 2);
#pragma unroll
            for (int nt = 0; nt < 8; nt++) {
                int col = n0 + warp_n * 64 + nt * 8 + (lane & 3) * 2;
                float2 v01 = make_float2(acc[mt][nt][0], acc[mt][nt][1]);
                float2 v23 = make_float2(acc[mt][nt][2], acc[mt][nt][3]);
                *reinterpret_cast<float2*>(out + (size_t)r0 * O_ + col) = v01;
                *reinterpret_cast<float2*>(out + (size_t)(r0 + 8) * O_ + col) = v23;
            }
        }
    } else {
#pragma unroll
        for (int mt = 0; mt < C::MT; mt++) {
            int t0 = m0 + warp_m * (C::MT * 16) + mt * 16 + (lane >> 2);
#pragma unroll
            for (int nt = 0; nt < 8; nt++) {
                int j = warp_n * 64 + nt * 8 + (lane & 3) * 2;
#pragma unroll
                for (int half = 0; half < 2; half++) {
                    int t = t0 + half * 8;
                    float wm = g_wmat[t * 8 + (j >> 4)];
                    __half2 hv(__float2half_rn(acc[mt][nt][half * 2 + 0] * wm),
                               __float2half_rn(acc[mt][nt][half * 2 + 1] * wm));
                    *reinterpret_cast<uint32_t*>(g_hw + (size_t)t * ER_ + j) =
                        *reinterpret_cast<uint32_t*>(&hv);
                }
            }
        }
        __syncthreads();
        if (tid == 0) {
            __threadfence();
            atomicAdd(&g_hdone, 1);
        }
    }
}

__global__ void __launch_bounds__(128, 2) k_gemm_all(float* __restrict__ out) {
    extern __shared__ __align__(128) char smem[];
    uint32_t sbase = smem_u32(smem);
    int bid = blockIdx.x, tid = threadIdx.x;
    if (bid < NB_H) {
        gemm_body<1>(sbase, bid * 64, 0, tid, nullptr);
    } else {
        int b = bid - NB_H;
        gemm_body<0>(sbase, (b & 63) * 128, (b >> 6) * 128, tid, out);
    }
}

// ---------------- launch ------------------------------------------------------
extern "C" void kernel_launch(void* const* d_in, const int* in_sizes, int n_in,
                              void* d_out, int out_size) {
    const float* x  = (const float*)d_in[0];
    const float* W  = (const float*)d_in[1];
    const float* gw = (const float*)d_in[2];
    const float* A  = (const float*)d_in[3];
    const float* B  = (const float*)d_in[4];
    float* out = (float*)d_out;

    cudaFuncSetAttribute(k_gemm_all, cudaFuncAttributeMaxDynamicSharedMemorySize,
                         Cfg<0>::SMEM);

    k_pre<<<NB_PRE, 256>>>(x, W, gw, A, B);
    k_gemm_all<<<NB_H + NB_MAIN, 128, Cfg<0>::SMEM>>>(out);
}